// round 9
// baseline (speedup 1.0000x reference)
#include <cuda_runtime.h>
#include <cuda_bf16.h>
#include <cuda_fp16.h>
#include <math.h>
#include <cstdint>

#define N 4096
#define D 256
#define NB (N / 128)
#define NTILES (NB * (NB + 1) / 2)   // 528, column-major: t = bj*(bj+1)/2 + bi
#define NLAB 512
#define GCTAS 148
#define PAIR_CAP (1u << 22)

// ---------------- device globals ----------------
__device__ __align__(16) __nv_bfloat16  g_normh[N * D]; // rows pre-swizzled: chunk c at c^(row&7)
__device__ int      g_lab[N];
__device__ float    g_tot[N];
__device__ float    g_pos[N];
__device__ float    g_loss_f;
__device__ int      g_bstart[NLAB + 1];
__device__ int      g_bidx[N];
__device__ unsigned g_npair;
__device__ unsigned g_pairab[PAIR_CAP];
__device__ float    g_pair_s[PAIR_CAP];
__device__ unsigned g_bar;   // grid barrier arrival counter
__device__ unsigned g_gen;   // grid barrier generation

// ---------------- smem layout ----------------
#define SMEM_A0   0
#define SMEM_A1   65536
#define SMEM_B    131072
#define SMEM_MBA0 196608
#define SMEM_MBA1 196616
#define SMEM_MBB  196624
#define SMEM_GT   196736

__device__ __forceinline__ uint32_t smem_u32(const void* p) {
    uint32_t a;
    asm("{ .reg .u64 t; cvta.to.shared.u64 t, %1; cvt.u32.u64 %0, t; }" : "=r"(a) : "l"(p));
    return a;
}
#define MBAR_INIT(mb, c)  asm volatile("mbarrier.init.shared.b64 [%0], %1;" :: "r"(mb), "r"(c) : "memory")
#define MBAR_EXPECT(mb, tx) asm volatile("mbarrier.arrive.expect_tx.shared.b64 _, [%0], %1;" :: "r"(mb), "r"(tx) : "memory")
#define BULK_LD(dst, src, sz, mb) \
    asm volatile("cp.async.bulk.shared::cta.global.mbarrier::complete_tx::bytes [%0], [%1], %2, [%3];" \
        :: "r"(dst), "l"(src), "r"(sz), "r"(mb) : "memory")

__device__ __forceinline__ void mbar_wait(uint32_t mb, uint32_t parity) {
    uint32_t done;
    asm volatile("{ .reg .pred p; mbarrier.try_wait.parity.acquire.cta.shared::cta.b64 p, [%1], %2; selp.b32 %0, 1, 0, p; }"
                 : "=r"(done) : "r"(mb), "r"(parity) : "memory");
    if (!done) {
        asm volatile("{ .reg .pred P1; W%=: mbarrier.try_wait.parity.acquire.cta.shared::cta.b64 P1, [%0], %1, 0x989680; @P1 bra.uni DN%=; bra.uni W%=; DN%=: }"
                     :: "r"(mb), "r"(parity) : "memory");
    }
}

#define LDSM4(r, a) \
    asm volatile("ldmatrix.sync.aligned.m8n8.x4.shared.b16 {%0,%1,%2,%3}, [%4];" \
        : "=r"((r)[0]), "=r"((r)[1]), "=r"((r)[2]), "=r"((r)[3]) : "r"(a))
#define LDSM4T(r, a) \
    asm volatile("ldmatrix.sync.aligned.m8n8.x4.trans.shared.b16 {%0,%1,%2,%3}, [%4];" \
        : "=r"((r)[0]), "=r"((r)[1]), "=r"((r)[2]), "=r"((r)[3]) : "r"(a))
#define MMA16816(d, a, b0_, b1_) \
    asm volatile("mma.sync.aligned.m16n8k16.row.col.f32.bf16.bf16.f32 " \
        "{%0,%1,%2,%3}, {%4,%5,%6,%7}, {%8,%9}, {%0,%1,%2,%3};" \
        : "+f"((d)[0]), "+f"((d)[1]), "+f"((d)[2]), "+f"((d)[3]) \
        : "r"((a)[0]), "r"((a)[1]), "r"((a)[2]), "r"((a)[3]), "r"(b0_), "r"(b1_))

// Sense-reversal grid barrier. All GCTAS CTAs resident (1/SM) -> no deadlock.
__device__ __forceinline__ void grid_barrier(int tid) {
    __syncthreads();
    if (tid == 0) {
        __threadfence();
        unsigned gen = *(volatile unsigned*)&g_gen;
        unsigned t = atomicAdd(&g_bar, 1u);
        if (t == GCTAS - 1) {
            *(volatile unsigned*)&g_bar = 0u;
            __threadfence();
            atomicAdd(&g_gen, 1u);
        } else {
            while (*(volatile unsigned*)&g_gen == gen) __nanosleep(32);
        }
        __threadfence();
    }
    __syncthreads();
}

__device__ __forceinline__ void tile_decode(int t, int& bi, int& bj) {
    int b = (int)((sqrtf(8.f * (float)t + 1.f) - 1.f) * 0.5f);
    while ((b + 1) * (b + 2) / 2 <= t) b++;
    while (b * (b + 1) / 2 > t) b--;
    bj = b;
    bi = t - b * (b + 1) / 2;
}

// =====================================================================
// ONE persistent kernel: norm+bucket | GEMM tot-sums | pair dots | loss
// =====================================================================
__global__ __launch_bounds__(512, 1) void k_all(const float* __restrict__ x,
                                                const void* __restrict__ labels,
                                                float* __restrict__ out) {
    extern __shared__ char smem[];
    const int tid = threadIdx.x, wid = tid >> 5, l = tid & 31;
    const int wm = wid & 3, wn = wid >> 2;
    const uint32_t sb = smem_u32(smem);
    const int cta = blockIdx.x;

    if (tid == 0) {
        MBAR_INIT(sb + SMEM_MBA0, 1);
        MBAR_INIT(sb + SMEM_MBA1, 1);
        MBAR_INIT(sb + SMEM_MBB, 1);
    }
    __syncthreads();

    // ---------------- Phase 0 ----------------
    if (cta == GCTAS - 1) {
        // Bucket CTA: label sniff + histogram + scans + scatter + pair emission.
        int* cnt  = (int*)smem;           // 512
        int* bufA = cnt + NLAB;           // 512
        int* bufB = bufA + NLAB;          // 512
        int* s_nz = bufB + NLAB;
        if (tid == 0) { *s_nz = 0; g_loss_f = 0.f; }
        cnt[tid] = 0;
        __syncthreads();
        const int* l32 = (const int*)labels;
        int nz = 0;
        #pragma unroll
        for (int i = tid; i < N / 2; i += NLAB) nz |= (l32[2 * i + 1] != 0);
        if (nz) atomicOr(s_nz, 1);
        __syncthreads();
        const bool is64 = (*s_nz == 0);
        #pragma unroll
        for (int r = tid; r < N; r += NLAB) {
            int lv = is64 ? (int)((const long long*)labels)[r] : l32[r];
            g_lab[r] = lv;
            atomicAdd(&cnt[lv], 1);
        }
        __syncthreads();
        const int n_t = cnt[tid];
        // scan row counts
        bufA[tid] = n_t;
        __syncthreads();
        int* sc = bufA; int* dst = bufB;
        #pragma unroll
        for (int o = 1; o < NLAB; o <<= 1) {
            int v = sc[tid];
            if (tid >= o) v += sc[tid - o];
            dst[tid] = v;
            int* tmp = sc; sc = dst; dst = tmp;
            __syncthreads();
        }
        const int row_excl = sc[tid] - n_t;
        g_bstart[tid] = row_excl;
        if (tid == NLAB - 1) g_bstart[NLAB] = N;
        cnt[tid] = row_excl;    // scatter cursor
        __syncthreads();
        // scan pair counts
        const int np_t = n_t * (n_t - 1) / 2;
        sc[tid] = np_t;         // sc currently holds row scan; reuse
        __syncthreads();
        int* sc2 = sc; int* dst2 = dst;
        #pragma unroll
        for (int o = 1; o < NLAB; o <<= 1) {
            int v = sc2[tid];
            if (tid >= o) v += sc2[tid - o];
            dst2[tid] = v;
            int* tmp = sc2; sc2 = dst2; dst2 = tmp;
            __syncthreads();
        }
        const int pair_excl = sc2[tid] - np_t;
        if (tid == NLAB - 1) g_npair = (unsigned)sc2[tid];
        __syncthreads();
        // scatter rows
        #pragma unroll
        for (int r = tid; r < N; r += NLAB) {
            int p = atomicAdd(&cnt[g_lab[r]], 1);
            g_bidx[p] = r;
        }
        __syncthreads();
        // emit pairs for this label
        unsigned pb = (unsigned)pair_excl;
        for (int a = 0; a < n_t - 1; a++) {
            unsigned ga = (unsigned)g_bidx[row_excl + a];
            for (int b = a + 1; b < n_t; b++) {
                if (pb < PAIR_CAP)
                    g_pairab[pb] = (ga << 12) | (unsigned)g_bidx[row_excl + b];
                pb++;
            }
        }
    } else {
        // Norm CTAs: 2 rows per iteration, 256 threads each.
        float* wsum = (float*)smem;       // [2][8]
        const int half = tid >> 8;
        const int sub = tid & 255;
        for (int pr = cta; pr < N / 2; pr += GCTAS - 1) {
            const int row = pr * 2 + half;
            float v = x[row * D + sub];
            float sq = v * v;
            #pragma unroll
            for (int o = 16; o > 0; o >>= 1) sq += __shfl_down_sync(0xffffffffu, sq, o);
            if ((sub & 31) == 0) wsum[half * 8 + (sub >> 5)] = sq;
            __syncthreads();
            float s = 0.f;
            #pragma unroll
            for (int w = 0; w < 8; w++) s += wsum[half * 8 + w];
            float denom = fmaxf(sqrtf(s), 1e-12f);
            int c = sub >> 3;
            int cs = c ^ (row & 7);
            g_normh[row * D + cs * 8 + (sub & 7)] = __float2bfloat16_rn(v / denom);
            if (sub == 0) { g_tot[row] = 0.f; g_pos[row] = 0.f; }
            __syncthreads();
        }
    }

    grid_barrier(tid);

    // ---------------- Phase 1: GEMM (unchanged R7 body) ----------------
    {
        const int s = (int)(((long)cta * NTILES) / GCTAS);
        const int e = (int)(((long)(cta + 1) * NTILES) / GCTAS);

        int aph[2] = {0, 0}, bph = 0;
        int ab = 0;
        bool a_issued = false;
        int prev_bj = -1;
        const half2 SC = __float2half2_rn(2.8853900817779268f);   // 2*log2(e)

        for (int t = s; t < e; t++) {
            int bi, bj;
            tile_decode(t, bi, bj);
            const bool diag = (bi == bj);
            const bool newcol = (bj != prev_bj);
            prev_bj = bj;
            const int iBase = bi * 128;
            const int jBase = bj * 128;

            __syncthreads();

            if (tid == 0) {
                if (newcol) {
                    MBAR_EXPECT(sb + SMEM_MBB, 65536u);
                    #pragma unroll
                    for (int q = 0; q < 8; q++)
                        BULK_LD(sb + SMEM_B + q * 8192,
                                (const char*)&g_normh[(size_t)jBase * D] + q * 8192, 8192u, sb + SMEM_MBB);
                }
                if (!diag && !a_issued) {
                    uint32_t mba = sb + (ab ? SMEM_MBA1 : SMEM_MBA0);
                    uint32_t abuf = (ab ? SMEM_A1 : SMEM_A0);
                    MBAR_EXPECT(mba, 65536u);
                    #pragma unroll
                    for (int q = 0; q < 8; q++)
                        BULK_LD(sb + abuf + q * 8192,
                                (const char*)&g_normh[(size_t)iBase * D] + q * 8192, 8192u, mba);
                }
            }

            if (newcol) { mbar_wait(sb + SMEM_MBB, bph); bph ^= 1; }
            if (!diag)  { mbar_wait(sb + (ab ? SMEM_MBA1 : SMEM_MBA0), aph[ab]); aph[ab] ^= 1; }
            __syncthreads();

            float acc[2][4][4];
            #pragma unroll
            for (int mt = 0; mt < 2; mt++)
                #pragma unroll
                for (int nt = 0; nt < 4; nt++)
                    #pragma unroll
                    for (int ee = 0; ee < 4; ee++) acc[mt][nt][ee] = 0.f;

            const uint32_t aspace = diag ? (uint32_t)SMEM_B : (ab ? (uint32_t)SMEM_A1 : (uint32_t)SMEM_A0);
            const int row_a = wm * 32 + (l & 15);
            const uint32_t abase = sb + aspace + (uint32_t)row_a * 512;
            const int rxa = row_a & 7;
            const int hia = (l >> 4);
            const int row_b = wn * 32 + (l & 7) + ((l & 16) ? 8 : 0);
            const uint32_t bbase = sb + SMEM_B + (uint32_t)row_b * 512;
            const int rxb = row_b & 7;
            const int hib = (l >> 3) & 1;

            #pragma unroll
            for (int ks = 0; ks < 16; ks++) {
                const uint32_t ka = (uint32_t)(((ks * 2 + hia) ^ rxa) << 4);
                const uint32_t kb = (uint32_t)(((ks * 2 + hib) ^ rxb) << 4);
                uint32_t A0[4], A1[4];
                LDSM4(A0, abase + ka);
                LDSM4(A1, abase + 8192 + ka);
                #pragma unroll
                for (int p = 0; p < 2; p++) {
                    uint32_t Bt[4];
                    LDSM4T(Bt, bbase + (uint32_t)p * 8192 + kb);
                    MMA16816(acc[0][2 * p],     A0, Bt[0], Bt[1]);
                    MMA16816(acc[0][2 * p + 1], A0, Bt[2], Bt[3]);
                    MMA16816(acc[1][2 * p],     A1, Bt[0], Bt[1]);
                    MMA16816(acc[1][2 * p + 1], A1, Bt[2], Bt[3]);
                }
            }
            __syncthreads();

            a_issued = false;
            if (t + 1 < e) {
                int bi2, bj2;
                tile_decode(t + 1, bi2, bj2);
                if (bi2 != bj2) {
                    const int nb = diag ? ab : (ab ^ 1);
                    if (tid == 0) {
                        uint32_t mba = sb + (nb ? SMEM_MBA1 : SMEM_MBA0);
                        uint32_t abuf = (nb ? SMEM_A1 : SMEM_A0);
                        MBAR_EXPECT(mba, 65536u);
                        #pragma unroll
                        for (int q = 0; q < 8; q++)
                            BULK_LD(sb + abuf + q * 8192,
                                    (const char*)&g_normh[(size_t)(bi2 * 128) * D] + q * 8192, 8192u, mba);
                    }
                    ab = nb;
                    a_issued = true;
                }
            }

            // epilogue: exp(2s) via f16x2 EX2, row + column tot sums
            half2 ctot2[4];
            #pragma unroll
            for (int nt = 0; nt < 4; nt++) ctot2[nt] = __float2half2_rn(0.f);

            half2 cidx[4];
            if (diag) {
                #pragma unroll
                for (int nt = 0; nt < 4; nt++) {
                    float c0 = (float)(wn * 32 + nt * 8 + (l & 3) * 2);
                    cidx[nt] = __floats2half2_rn(c0, c0 + 1.0f);
                }
            }

            #pragma unroll
            for (int mt = 0; mt < 2; mt++) {
                #pragma unroll
                for (int half_ = 0; half_ < 2; half_++) {
                    const int row_local = wm * 32 + mt * 16 + half_ * 8 + (l >> 2);
                    const int gi = iBase + row_local;
                    half2 t2 = __float2half2_rn(0.f);
                    if (diag) {
                        const half2 r2 = __float2half2_rn((float)row_local);
                        #pragma unroll
                        for (int nt = 0; nt < 4; nt++) {
                            half2 h = __floats2half2_rn(acc[mt][nt][half_ * 2], acc[mt][nt][half_ * 2 + 1]);
                            half2 ex = h2exp2(__hmul2(h, SC));
                            half2 eq = __heq2(cidx[nt], r2);
                            ex = __hsub2(ex, __hmul2(ex, eq));
                            t2 = __hadd2(t2, ex);
                            ctot2[nt] = __hadd2(ctot2[nt], ex);
                        }
                    } else {
                        #pragma unroll
                        for (int nt = 0; nt < 4; nt++) {
                            half2 h = __floats2half2_rn(acc[mt][nt][half_ * 2], acc[mt][nt][half_ * 2 + 1]);
                            half2 ex = h2exp2(__hmul2(h, SC));
                            t2 = __hadd2(t2, ex);
                            ctot2[nt] = __hadd2(ctot2[nt], ex);
                        }
                    }
                    float2 f = __half22float2(t2);
                    float tt = f.x + f.y;
                    tt += __shfl_xor_sync(0xffffffffu, tt, 1);
                    tt += __shfl_xor_sync(0xffffffffu, tt, 2);
                    if ((l & 3) == 0) atomicAdd(&g_tot[gi], tt);
                }
            }
            if (!diag) {
                #pragma unroll
                for (int nt = 0; nt < 4; nt++) {
                    uint32_t v = *(uint32_t*)&ctot2[nt];
                    #pragma unroll
                    for (int m = 4; m <= 16; m <<= 1) {
                        uint32_t o = __shfl_xor_sync(0xffffffffu, v, m);
                        half2 hv = *(half2*)&v, ho = *(half2*)&o;
                        hv = __hadd2(hv, ho);
                        v = *(uint32_t*)&hv;
                    }
                    if (l < 4) {
                        float2 fc = __half22float2(*(half2*)&v);
                        int c0 = wn * 32 + nt * 8 + l * 2;
                        atomicAdd(&g_tot[jBase + c0], fc.x);
                        atomicAdd(&g_tot[jBase + c0 + 1], fc.y);
                    }
                }
            }
        }
    }

    grid_barrier(tid);

    // ---------------- Phase 2: warp-per-pair exact dots + pos ----------------
    {
        unsigned np = g_npair;
        if (np > PAIR_CAP) np = PAIR_CAP;
        const unsigned gw = (unsigned)(cta * 16 + wid);
        const unsigned nw = GCTAS * 16;
        for (unsigned p = gw; p < np; p += nw) {
            unsigned ab = g_pairab[p];
            int a = (int)(ab >> 12);
            int b = (int)(ab & 0xfffu);
            const uint4 xa = *(const uint4*)&g_normh[(size_t)a * D + (size_t)((l ^ (a & 7)) * 8)];
            const uint4 xb = *(const uint4*)&g_normh[(size_t)b * D + (size_t)((l ^ (b & 7)) * 8)];
            float s = 0.f;
            const uint32_t* qa = (const uint32_t*)&xa;
            const uint32_t* qb = (const uint32_t*)&xb;
            #pragma unroll
            for (int q = 0; q < 4; q++) {
                float2 fa = __bfloat1622float2(*(const __nv_bfloat162*)&qa[q]);
                float2 fb = __bfloat1622float2(*(const __nv_bfloat162*)&qb[q]);
                s += fa.x * fb.x + fa.y * fb.y;
            }
            #pragma unroll
            for (int o = 16; o > 0; o >>= 1) s += __shfl_xor_sync(0xffffffffu, s, o);
            if (l == 0) {
                g_pair_s[p] = s;
                float e = __expf(2.0f * s);
                atomicAdd(&g_pos[a], e);
                atomicAdd(&g_pos[b], e);
            }
        }
    }

    grid_barrier(tid);

    // ---------------- Phase 3: thread-per-pair loss ----------------
    {
        unsigned np = g_npair;
        if (np > PAIR_CAP) np = PAIR_CAP;
        float lsum = 0.f;
        for (unsigned p = (unsigned)(cta * 512 + tid); p < np; p += GCTAS * 512) {
            unsigned ab = g_pairab[p];
            int a = (int)(ab >> 12);
            int b = (int)(ab & 0xfffu);
            float s = g_pair_s[p];
            float e = __expf(2.0f * s);
            float nega = g_tot[a] - g_pos[a];
            float negb = g_tot[b] - g_pos[b];
            lsum += logf(e + nega) + logf(e + negb) - 4.0f * s;
        }
        #pragma unroll
        for (int o = 16; o > 0; o >>= 1) lsum += __shfl_down_sync(0xffffffffu, lsum, o);
        float* sred = (float*)smem;   // 16 floats (smem free after phase 1/2)
        __syncthreads();
        if (l == 0) sred[wid] = lsum;
        __syncthreads();
        if (tid == 0) {
            float L = 0.f;
            #pragma unroll
            for (int w = 0; w < 16; w++) L += sred[w];
            if (L != 0.f) atomicAdd(&g_loss_f, L);
        }
    }

    grid_barrier(tid);

    if (cta == 0 && tid == 0)
        out[0] = g_loss_f / (float)(2u * g_npair);
}

// ---------------- launch ----------------
extern "C" void kernel_launch(void* const* d_in, const int* in_sizes, int n_in,
                              void* d_out, int out_size) {
    const float* x = (const float*)d_in[0];
    const void* labels = d_in[1];

    static bool attr_done = false;
    if (!attr_done) {
        cudaFuncSetAttribute(k_all, cudaFuncAttributeMaxDynamicSharedMemorySize, SMEM_GT);
        attr_done = true;
    }

    k_all<<<GCTAS, 512, SMEM_GT>>>(x, labels, (float*)d_out);
}

// round 10
// speedup vs baseline: 1.0355x; 1.0355x over previous
#include <cuda_runtime.h>
#include <cuda_bf16.h>
#include <cuda_fp16.h>
#include <math.h>
#include <cstdint>

#define N 4096
#define D 256
#define NB (N / 128)
#define NTILES (NB * (NB + 1) / 2)   // 528, column-major: t = bj*(bj+1)/2 + bi
#define NLAB 512
#define GCTAS 148
#define PAIR_CAP (1u << 23)

// ---------------- device globals ----------------
__device__ __align__(16) __nv_bfloat16  g_normh[N * D]; // rows pre-swizzled: chunk c at c^(row&7)
__device__ __align__(16) __half         g_smat[(size_t)N * N]; // sim (upper tiles valid)
__device__ int      g_lab[N];
__device__ float    g_tot[N];
__device__ float    g_pos[N];
__device__ float    g_loss_f;
__device__ int      g_bstart[NLAB + 1];
__device__ int      g_bidx[N];
__device__ unsigned g_npair;
__device__ unsigned g_pairab[PAIR_CAP];
__device__ unsigned g_bar;
__device__ unsigned g_gen;

// ---------------- smem layout for k_gemm ----------------
#define SMEM_A0   0
#define SMEM_A1   65536
#define SMEM_B    131072
#define SMEM_MBA0 196608
#define SMEM_MBA1 196616
#define SMEM_MBB  196624
#define SMEM_GT   196736

__device__ __forceinline__ uint32_t smem_u32(const void* p) {
    uint32_t a;
    asm("{ .reg .u64 t; cvta.to.shared.u64 t, %1; cvt.u32.u64 %0, t; }" : "=r"(a) : "l"(p));
    return a;
}
#define MBAR_INIT(mb, c)  asm volatile("mbarrier.init.shared.b64 [%0], %1;" :: "r"(mb), "r"(c) : "memory")
#define MBAR_EXPECT(mb, tx) asm volatile("mbarrier.arrive.expect_tx.shared.b64 _, [%0], %1;" :: "r"(mb), "r"(tx) : "memory")
#define BULK_LD(dst, src, sz, mb) \
    asm volatile("cp.async.bulk.shared::cta.global.mbarrier::complete_tx::bytes [%0], [%1], %2, [%3];" \
        :: "r"(dst), "l"(src), "r"(sz), "r"(mb) : "memory")

__device__ __forceinline__ void mbar_wait(uint32_t mb, uint32_t parity) {
    uint32_t done;
    asm volatile("{ .reg .pred p; mbarrier.try_wait.parity.acquire.cta.shared::cta.b64 p, [%1], %2; selp.b32 %0, 1, 0, p; }"
                 : "=r"(done) : "r"(mb), "r"(parity) : "memory");
    if (!done) {
        asm volatile("{ .reg .pred P1; W%=: mbarrier.try_wait.parity.acquire.cta.shared::cta.b64 P1, [%0], %1, 0x989680; @P1 bra.uni DN%=; bra.uni W%=; DN%=: }"
                     :: "r"(mb), "r"(parity) : "memory");
    }
}

#define LDSM4(r, a) \
    asm volatile("ldmatrix.sync.aligned.m8n8.x4.shared.b16 {%0,%1,%2,%3}, [%4];" \
        : "=r"((r)[0]), "=r"((r)[1]), "=r"((r)[2]), "=r"((r)[3]) : "r"(a))
#define LDSM4T(r, a) \
    asm volatile("ldmatrix.sync.aligned.m8n8.x4.trans.shared.b16 {%0,%1,%2,%3}, [%4];" \
        : "=r"((r)[0]), "=r"((r)[1]), "=r"((r)[2]), "=r"((r)[3]) : "r"(a))
#define MMA16816(d, a, b0_, b1_) \
    asm volatile("mma.sync.aligned.m16n8k16.row.col.f32.bf16.bf16.f32 " \
        "{%0,%1,%2,%3}, {%4,%5,%6,%7}, {%8,%9}, {%0,%1,%2,%3};" \
        : "+f"((d)[0]), "+f"((d)[1]), "+f"((d)[2]), "+f"((d)[3]) \
        : "r"((a)[0]), "r"((a)[1]), "r"((a)[2]), "r"((a)[3]), "r"(b0_), "r"(b1_))

// Sense-reversal grid barrier (used by k_tail; exactly GCTAS CTAs resident).
__device__ __forceinline__ void grid_barrier(int tid) {
    __syncthreads();
    if (tid == 0) {
        __threadfence();
        unsigned gen = *(volatile unsigned*)&g_gen;
        unsigned t = atomicAdd(&g_bar, 1u);
        if (t == GCTAS - 1) {
            *(volatile unsigned*)&g_bar = 0u;
            __threadfence();
            atomicAdd(&g_gen, 1u);
        } else {
            while (*(volatile unsigned*)&g_gen == gen) __nanosleep(32);
        }
        __threadfence();
    }
    __syncthreads();
}

__device__ __forceinline__ void tile_decode(int t, int& bi, int& bj) {
    int b = (int)((sqrtf(8.f * (float)t + 1.f) - 1.f) * 0.5f);
    while ((b + 1) * (b + 2) / 2 <= t) b++;
    while (b * (b + 1) / 2 > t) b--;
    bj = b;
    bi = t - b * (b + 1) / 2;
}

// ---------------- kernels ----------------
__global__ void k_norm(const float* __restrict__ x) {
    int row = blockIdx.x;
    int t = threadIdx.x;  // 256 == D
    float v = x[row * D + t];
    float sq = v * v;
    #pragma unroll
    for (int o = 16; o > 0; o >>= 1) sq += __shfl_down_sync(0xffffffffu, sq, o);
    __shared__ float wsum[8];
    if ((t & 31) == 0) wsum[t >> 5] = sq;
    __syncthreads();
    float s = 0.f;
    #pragma unroll
    for (int w = 0; w < 8; w++) s += wsum[w];
    float denom = fmaxf(sqrtf(s), 1e-12f);
    int c = t >> 3;
    int cs = c ^ (row & 7);
    g_normh[row * D + cs * 8 + (t & 7)] = __float2bfloat16_rn(v / denom);
    if (t == 0) { g_tot[row] = 0.f; g_pos[row] = 0.f; }
}

// Labels: sniff + bucket + pair-list emission. One block, 512 threads.
__global__ void k_bucket(const void* __restrict__ labels) {
    __shared__ int s_nz;
    __shared__ int cnt[NLAB];
    __shared__ int buf[2][NLAB];
    int t = threadIdx.x;   // 512
    if (t == 0) { s_nz = 0; g_loss_f = 0.f; }
    cnt[t] = 0;
    __syncthreads();
    const int* l32 = (const int*)labels;
    int nz = 0;
    #pragma unroll
    for (int i = t; i < N / 2; i += NLAB) nz |= (l32[2 * i + 1] != 0);
    if (nz) atomicOr(&s_nz, 1);
    __syncthreads();
    const bool is64 = (s_nz == 0);
    #pragma unroll
    for (int r = t; r < N; r += NLAB) {
        int lv = is64 ? (int)((const long long*)labels)[r] : l32[r];
        g_lab[r] = lv;
        atomicAdd(&cnt[lv], 1);
    }
    __syncthreads();
    const int n_t = cnt[t];
    buf[0][t] = n_t;
    __syncthreads();
    int src = 0;
    #pragma unroll
    for (int o = 1; o < NLAB; o <<= 1) {
        int v = buf[src][t];
        if (t >= o) v += buf[src][t - o];
        buf[1 - src][t] = v;
        src = 1 - src;
        __syncthreads();
    }
    const int row_excl = buf[src][t] - n_t;
    g_bstart[t] = row_excl;
    if (t == NLAB - 1) g_bstart[NLAB] = N;
    cnt[t] = row_excl;
    __syncthreads();
    const int np_t = n_t * (n_t - 1) / 2;
    buf[0][t] = np_t;
    __syncthreads();
    src = 0;
    #pragma unroll
    for (int o = 1; o < NLAB; o <<= 1) {
        int v = buf[src][t];
        if (t >= o) v += buf[src][t - o];
        buf[1 - src][t] = v;
        src = 1 - src;
        __syncthreads();
    }
    const int pair_excl = buf[src][t] - np_t;
    if (t == NLAB - 1) g_npair = (unsigned)buf[src][t];
    __syncthreads();
    #pragma unroll
    for (int r = t; r < N; r += NLAB) {
        int p = atomicAdd(&cnt[g_lab[r]], 1);
        g_bidx[p] = r;
    }
    __syncthreads();
    unsigned pb = (unsigned)pair_excl;
    for (int a = 0; a < n_t - 1; a++) {
        unsigned ga = (unsigned)g_bidx[row_excl + a];
        for (int b = a + 1; b < n_t; b++) {
            if (pb < PAIR_CAP)
                g_pairab[pb] = (ga << 12) | (unsigned)g_bidx[row_excl + b];
            pb++;
        }
    }
}

// Persistent bf16 mma.sync GEMM (R7 body) + half s-matrix store.
__global__ __launch_bounds__(512, 1) void k_gemm() {
    extern __shared__ char smem[];
    const int tid = threadIdx.x, wid = tid >> 5, l = tid & 31;
    const int wm = wid & 3, wn = wid >> 2;
    const uint32_t sb = smem_u32(smem);

    if (tid == 0) {
        MBAR_INIT(sb + SMEM_MBA0, 1);
        MBAR_INIT(sb + SMEM_MBA1, 1);
        MBAR_INIT(sb + SMEM_MBB, 1);
    }
    __syncthreads();

    const int s = (int)(((long)blockIdx.x * NTILES) / GCTAS);
    const int e = (int)(((long)(blockIdx.x + 1) * NTILES) / GCTAS);

    int aph[2] = {0, 0}, bph = 0;
    int ab = 0;
    bool a_issued = false;
    int prev_bj = -1;
    const half2 SC = __float2half2_rn(2.8853900817779268f);   // 2*log2(e)

    for (int t = s; t < e; t++) {
        int bi, bj;
        tile_decode(t, bi, bj);
        const bool diag = (bi == bj);
        const bool newcol = (bj != prev_bj);
        prev_bj = bj;
        const int iBase = bi * 128;
        const int jBase = bj * 128;

        __syncthreads();

        if (tid == 0) {
            if (newcol) {
                MBAR_EXPECT(sb + SMEM_MBB, 65536u);
                #pragma unroll
                for (int q = 0; q < 8; q++)
                    BULK_LD(sb + SMEM_B + q * 8192,
                            (const char*)&g_normh[(size_t)jBase * D] + q * 8192, 8192u, sb + SMEM_MBB);
            }
            if (!diag && !a_issued) {
                uint32_t mba = sb + (ab ? SMEM_MBA1 : SMEM_MBA0);
                uint32_t abuf = (ab ? SMEM_A1 : SMEM_A0);
                MBAR_EXPECT(mba, 65536u);
                #pragma unroll
                for (int q = 0; q < 8; q++)
                    BULK_LD(sb + abuf + q * 8192,
                            (const char*)&g_normh[(size_t)iBase * D] + q * 8192, 8192u, mba);
            }
        }

        if (newcol) { mbar_wait(sb + SMEM_MBB, bph); bph ^= 1; }
        if (!diag)  { mbar_wait(sb + (ab ? SMEM_MBA1 : SMEM_MBA0), aph[ab]); aph[ab] ^= 1; }
        __syncthreads();

        float acc[2][4][4];
        #pragma unroll
        for (int mt = 0; mt < 2; mt++)
            #pragma unroll
            for (int nt = 0; nt < 4; nt++)
                #pragma unroll
                for (int ee = 0; ee < 4; ee++) acc[mt][nt][ee] = 0.f;

        const uint32_t aspace = diag ? (uint32_t)SMEM_B : (ab ? (uint32_t)SMEM_A1 : (uint32_t)SMEM_A0);
        const int row_a = wm * 32 + (l & 15);
        const uint32_t abase = sb + aspace + (uint32_t)row_a * 512;
        const int rxa = row_a & 7;
        const int hia = (l >> 4);
        const int row_b = wn * 32 + (l & 7) + ((l & 16) ? 8 : 0);
        const uint32_t bbase = sb + SMEM_B + (uint32_t)row_b * 512;
        const int rxb = row_b & 7;
        const int hib = (l >> 3) & 1;

        #pragma unroll
        for (int ks = 0; ks < 16; ks++) {
            const uint32_t ka = (uint32_t)(((ks * 2 + hia) ^ rxa) << 4);
            const uint32_t kb = (uint32_t)(((ks * 2 + hib) ^ rxb) << 4);
            uint32_t A0[4], A1[4];
            LDSM4(A0, abase + ka);
            LDSM4(A1, abase + 8192 + ka);
            #pragma unroll
            for (int p = 0; p < 2; p++) {
                uint32_t Bt[4];
                LDSM4T(Bt, bbase + (uint32_t)p * 8192 + kb);
                MMA16816(acc[0][2 * p],     A0, Bt[0], Bt[1]);
                MMA16816(acc[0][2 * p + 1], A0, Bt[2], Bt[3]);
                MMA16816(acc[1][2 * p],     A1, Bt[0], Bt[1]);
                MMA16816(acc[1][2 * p + 1], A1, Bt[2], Bt[3]);
            }
        }
        __syncthreads();

        a_issued = false;
        if (t + 1 < e) {
            int bi2, bj2;
            tile_decode(t + 1, bi2, bj2);
            if (bi2 != bj2) {
                const int nb = diag ? ab : (ab ^ 1);
                if (tid == 0) {
                    uint32_t mba = sb + (nb ? SMEM_MBA1 : SMEM_MBA0);
                    uint32_t abuf = (nb ? SMEM_A1 : SMEM_A0);
                    MBAR_EXPECT(mba, 65536u);
                    #pragma unroll
                    for (int q = 0; q < 8; q++)
                        BULK_LD(sb + abuf + q * 8192,
                                (const char*)&g_normh[(size_t)(bi2 * 128) * D] + q * 8192, 8192u, mba);
                }
                ab = nb;
                a_issued = true;
            }
        }

        // ---- store s tile to g_smat (half) ----
        #pragma unroll
        for (int mt = 0; mt < 2; mt++) {
            #pragma unroll
            for (int half_ = 0; half_ < 2; half_++) {
                const int gi = iBase + wm * 32 + mt * 16 + half_ * 8 + (l >> 2);
                #pragma unroll
                for (int nt = 0; nt < 4; nt++) {
                    const int col = jBase + wn * 32 + nt * 8 + (l & 3) * 2;
                    half2 hv = __floats2half2_rn(acc[mt][nt][half_ * 2], acc[mt][nt][half_ * 2 + 1]);
                    *(half2*)&g_smat[(size_t)gi * N + col] = hv;
                }
            }
        }

        // ---- epilogue: exp(2s) via f16x2 EX2, row + column tot sums ----
        half2 ctot2[4];
        #pragma unroll
        for (int nt = 0; nt < 4; nt++) ctot2[nt] = __float2half2_rn(0.f);

        half2 cidx[4];
        if (diag) {
            #pragma unroll
            for (int nt = 0; nt < 4; nt++) {
                float c0 = (float)(wn * 32 + nt * 8 + (l & 3) * 2);
                cidx[nt] = __floats2half2_rn(c0, c0 + 1.0f);
            }
        }

        #pragma unroll
        for (int mt = 0; mt < 2; mt++) {
            #pragma unroll
            for (int half_ = 0; half_ < 2; half_++) {
                const int row_local = wm * 32 + mt * 16 + half_ * 8 + (l >> 2);
                const int gi = iBase + row_local;
                half2 t2 = __float2half2_rn(0.f);
                if (diag) {
                    const half2 r2 = __float2half2_rn((float)row_local);
                    #pragma unroll
                    for (int nt = 0; nt < 4; nt++) {
                        half2 h = __floats2half2_rn(acc[mt][nt][half_ * 2], acc[mt][nt][half_ * 2 + 1]);
                        half2 ex = h2exp2(__hmul2(h, SC));
                        half2 eq = __heq2(cidx[nt], r2);
                        ex = __hsub2(ex, __hmul2(ex, eq));
                        t2 = __hadd2(t2, ex);
                        ctot2[nt] = __hadd2(ctot2[nt], ex);
                    }
                } else {
                    #pragma unroll
                    for (int nt = 0; nt < 4; nt++) {
                        half2 h = __floats2half2_rn(acc[mt][nt][half_ * 2], acc[mt][nt][half_ * 2 + 1]);
                        half2 ex = h2exp2(__hmul2(h, SC));
                        t2 = __hadd2(t2, ex);
                        ctot2[nt] = __hadd2(ctot2[nt], ex);
                    }
                }
                float2 f = __half22float2(t2);
                float tt = f.x + f.y;
                tt += __shfl_xor_sync(0xffffffffu, tt, 1);
                tt += __shfl_xor_sync(0xffffffffu, tt, 2);
                if ((l & 3) == 0) atomicAdd(&g_tot[gi], tt);
            }
        }
        if (!diag) {
            #pragma unroll
            for (int nt = 0; nt < 4; nt++) {
                uint32_t v = *(uint32_t*)&ctot2[nt];
                #pragma unroll
                for (int m = 4; m <= 16; m <<= 1) {
                    uint32_t o = __shfl_xor_sync(0xffffffffu, v, m);
                    half2 hv = *(half2*)&v, ho = *(half2*)&o;
                    hv = __hadd2(hv, ho);
                    v = *(uint32_t*)&hv;
                }
                if (l < 4) {
                    float2 fc = __half22float2(*(half2*)&v);
                    int c0 = wn * 32 + nt * 8 + l * 2;
                    atomicAdd(&g_tot[jBase + c0], fc.x);
                    atomicAdd(&g_tot[jBase + c0 + 1], fc.y);
                }
            }
        }
    }
}

// Persistent tail: phase A pos accumulation, barrier, phase B loss + finalize.
__global__ __launch_bounds__(512, 1) void k_tail(float* __restrict__ out) {
    const int tid = threadIdx.x;
    const int cta = blockIdx.x;
    unsigned np = g_npair;
    if (np > PAIR_CAP) np = PAIR_CAP;

    // Phase A: thread-per-pair, read s from smat, accumulate pos.
    for (unsigned p = (unsigned)(cta * 512 + tid); p < np; p += GCTAS * 512) {
        unsigned ab = g_pairab[p];
        int a = (int)(ab >> 12);
        int b = (int)(ab & 0xfffu);
        float s = __half2float(g_smat[(size_t)a * N + b]);
        float e = __expf(2.0f * s);
        atomicAdd(&g_pos[a], e);
        atomicAdd(&g_pos[b], e);
    }

    grid_barrier(tid);

    // Phase B: thread-per-pair loss terms.
    float lsum = 0.f;
    for (unsigned p = (unsigned)(cta * 512 + tid); p < np; p += GCTAS * 512) {
        unsigned ab = g_pairab[p];
        int a = (int)(ab >> 12);
        int b = (int)(ab & 0xfffu);
        float s = __half2float(g_smat[(size_t)a * N + b]);
        float e = __expf(2.0f * s);
        float nega = g_tot[a] - g_pos[a];
        float negb = g_tot[b] - g_pos[b];
        lsum += logf(e + nega) + logf(e + negb) - 4.0f * s;
    }
    #pragma unroll
    for (int o = 16; o > 0; o >>= 1) lsum += __shfl_down_sync(0xffffffffu, lsum, o);
    __shared__ float sred[16];
    if ((tid & 31) == 0) sred[tid >> 5] = lsum;
    __syncthreads();
    if (tid == 0) {
        float L = 0.f;
        #pragma unroll
        for (int w = 0; w < 16; w++) L += sred[w];
        if (L != 0.f) atomicAdd(&g_loss_f, L);
    }

    grid_barrier(tid);

    if (cta == 0 && tid == 0)
        out[0] = g_loss_f / (float)(2u * np);
}

// ---------------- launch ----------------
extern "C" void kernel_launch(void* const* d_in, const int* in_sizes, int n_in,
                              void* d_out, int out_size) {
    const float* x = (const float*)d_in[0];
    const void* labels = d_in[1];

    static bool attr_done = false;
    if (!attr_done) {
        cudaFuncSetAttribute(k_gemm, cudaFuncAttributeMaxDynamicSharedMemorySize, SMEM_GT);
        attr_done = true;
    }

    k_norm<<<N, 256>>>(x);
    k_bucket<<<1, NLAB>>>(labels);
    k_gemm<<<GCTAS, 512, SMEM_GT>>>();
    k_tail<<<GCTAS, 512>>>((float*)d_out);
}